// round 15
// baseline (speedup 1.0000x reference)
#include <cuda_runtime.h>
#include <cuda_fp16.h>
#include <math.h>
#include <stdint.h>

// Problem constants
#define T_   1024
#define B_   8
#define D_   1024
#define H_   16
#define DH_  64
#define FF_  4096
#define M_   (T_ * B_)          // 8192
#define MD_  (8388608)          // M_ * D_
#define SCALE_ 0.125f
#define BG_  0.1f

// fp32 scratch:
// 0:xn 1-3:qkv 4:attnb 5:y 6-8:yW 9-11:xU 12:src 13:sn 14:ffo 15-18:ff1
__device__ float g_buf[19ull * 8388608ull];
// fp16 operand scratch
__device__ __half g_Ah[33554432];        // A (rounded to fp16), up to M x FF
__device__ __half g_Bh[4194304];         // B (rounded to fp16), [N,K]

// ---------------------------------------------------------------------------
// PTX helpers
// ---------------------------------------------------------------------------
__device__ __forceinline__ uint32_t smem_u32(const void* p) {
    uint32_t a;
    asm("{ .reg .u64 t; cvta.to.shared.u64 t, %1; cvt.u32.u64 %0, t; }"
        : "=r"(a) : "l"(p));
    return a;
}
__device__ __forceinline__ void cp16(uint32_t s, const void* g) {
    asm volatile("cp.async.cg.shared.global [%0], [%1], 16;" :: "r"(s), "l"(g));
}
__device__ __forceinline__ void cp_commit() {
    asm volatile("cp.async.commit_group;" ::: "memory");
}
__device__ __forceinline__ void cp_wait1() {
    asm volatile("cp.async.wait_group 1;" ::: "memory");
}
__device__ __forceinline__ void ldsm4(uint32_t (&r)[4], uint32_t addr) {
    asm volatile("ldmatrix.sync.aligned.m8n8.x4.shared.b16 {%0,%1,%2,%3}, [%4];"
        : "=r"(r[0]), "=r"(r[1]), "=r"(r[2]), "=r"(r[3]) : "r"(addr));
}
// fp16 MMA, fp32 accumulate
#define MMA(d, a, b) \
    asm volatile("mma.sync.aligned.m16n8k16.row.col.f32.f16.f16.f32 " \
        "{%0,%1,%2,%3}, {%4,%5,%6,%7}, {%8,%9}, {%0,%1,%2,%3};" \
        : "+f"((d)[0]), "+f"((d)[1]), "+f"((d)[2]), "+f"((d)[3]) \
        : "r"((a)[0]), "r"((a)[1]), "r"((a)[2]), "r"((a)[3]), \
          "r"((b)[0]), "r"((b)[1]))

// ---------------------------------------------------------------------------
// fp32 -> fp16 convert (A operand)
// ---------------------------------------------------------------------------
__global__ __launch_bounds__(256) void convA_kernel(
    const float* __restrict__ in, __half* __restrict__ oh, int n4)
{
    int i = blockIdx.x * 256 + threadIdx.x;
    if (i >= n4) return;
    float4 v = ((const float4*)in)[i];
    ((__half2*)oh)[2 * i]     = __floats2half2_rn(v.x, v.y);
    ((__half2*)oh)[2 * i + 1] = __floats2half2_rn(v.z, v.w);
}

// ---------------------------------------------------------------------------
// Weight transpose + fp16 convert: fp32 [K,N] -> fp16 [N,K]
// ---------------------------------------------------------------------------
__global__ __launch_bounds__(256) void transB_kernel(
    const float* __restrict__ in, __half* __restrict__ oh, int Kd, int Nd)
{
    __shared__ float t[32][33];
    int n0 = blockIdx.x * 32, k0 = blockIdx.y * 32;
    int tx = threadIdx.x, ty = threadIdx.y;      // (32, 8)
    #pragma unroll
    for (int j = 0; j < 32; j += 8)
        t[ty + j][tx] = in[(size_t)(k0 + ty + j) * Nd + n0 + tx];
    __syncthreads();
    #pragma unroll
    for (int j = 0; j < 32; j += 8) {
        size_t o = (size_t)(n0 + ty + j) * Kd + k0 + tx;
        oh[o] = __float2half_rn(t[tx][ty + j]);
    }
}

// ---------------------------------------------------------------------------
// fp16 GEMM: C[M,N] = A[M,K] @ B[N,K]^T  (fp32 accumulate)
// CTA 256x128x32, 8 warps (64x64 each), 3-stage cp.async, 1 barrier/K-tile.
// ---------------------------------------------------------------------------
#define BM 256
#define BN 128
#define BK 32
#define STAGES 3
#define AROW 40                                // padded row stride (fp16)
#define A_BYTES (BM * AROW * 2)                // 20480
#define B_BYTES (BN * AROW * 2)                // 10240
#define STG_BYTES (A_BYTES + B_BYTES)          // 30720
#define GEMM_SMEM (STAGES * STG_BYTES)         // 92160

__global__ __launch_bounds__(256) void mma_gemm(
    const __half* __restrict__ Ah, const __half* __restrict__ Bh,
    float* __restrict__ C, int M, int N, int K,
    const float* __restrict__ bias, int relu)
{
    extern __shared__ char smem[];
    const uint32_t sbase = smem_u32(smem);
    const int tid = threadIdx.x, wid = tid >> 5, lane = tid & 31;
    const int wm = wid & 3, wn = wid >> 2;          // warp tile 64m x 64n
    const size_t arow0 = (size_t)blockIdx.y * BM;
    const size_t brow0 = (size_t)blockIdx.x * BN;
    const __half* gA = Ah + arow0 * K;
    const __half* gB = Bh + brow0 * K;
    const int KT = K / BK;

    auto load_stage = [&](int t) {
        uint32_t sb = sbase + (uint32_t)(t % STAGES) * STG_BYTES;
        size_t ko = (size_t)t * BK;
        #pragma unroll
        for (int j = 0; j < 4; j++) {              // A: 1024 16B-chunks
            int cid = tid + j * 256;
            int row = cid >> 2, c16 = cid & 3;
            cp16(sb + (uint32_t)(row * AROW + c16 * 8) * 2,
                 (const char*)(gA + (size_t)row * K + ko) + c16 * 16);
        }
        #pragma unroll
        for (int j = 0; j < 2; j++) {              // B: 512 chunks
            int cid = tid + j * 256;
            int row = cid >> 2, c16 = cid & 3;
            cp16(sb + A_BYTES + (uint32_t)(row * AROW + c16 * 8) * 2,
                 (const char*)(gB + (size_t)row * K + ko) + c16 * 16);
        }
        cp_commit();
    };

    load_stage(0);
    load_stage(1);

    float acc[4][8][4];
    #pragma unroll
    for (int i = 0; i < 4; i++)
        #pragma unroll
        for (int j = 0; j < 8; j++)
            #pragma unroll
            for (int q = 0; q < 4; q++) acc[i][j][q] = 0.f;

    const int lrowA = lane & 15, lcolA = (lane >> 4) * 8;
    const int lrowB = (lane & 7) + ((lane >> 4) << 3);
    const int lcolB = ((lane >> 3) & 1) * 8;

    for (int t = 0; t < KT; t++) {
        cp_wait1();
        __syncthreads();
        if (t + 2 < KT) load_stage(t + 2);

        uint32_t sb = sbase + (uint32_t)(t % STAGES) * STG_BYTES;
        uint32_t sA = sb, sB = sb + A_BYTES;

        #pragma unroll
        for (int kk = 0; kk < BK; kk += 16) {
            uint32_t aH[4][4], bH[8][2];
            #pragma unroll
            for (int mi = 0; mi < 4; mi++) {
                uint32_t off =
                    (uint32_t)((wm * 64 + mi * 16 + lrowA) * AROW + kk + lcolA) * 2;
                ldsm4(aH[mi], sA + off);
            }
            #pragma unroll
            for (int np = 0; np < 4; np++) {
                uint32_t off =
                    (uint32_t)((wn * 64 + np * 16 + lrowB) * AROW + kk + lcolB) * 2;
                uint32_t r[4];
                ldsm4(r, sB + off);
                bH[2 * np][0] = r[0]; bH[2 * np][1] = r[1];
                bH[2 * np + 1][0] = r[2]; bH[2 * np + 1][1] = r[3];
            }
            #pragma unroll
            for (int mi = 0; mi < 4; mi++)
                #pragma unroll
                for (int ni = 0; ni < 8; ni++)
                    MMA(acc[mi][ni], aH[mi], bH[ni]);
        }
    }

    // epilogue: registers -> GMEM (float2), fused bias/relu
    const int g = lane >> 2, tq = (lane & 3) * 2;
    const int crow = blockIdx.y * BM + wm * 64;
    const int ccol = blockIdx.x * BN + wn * 64;
    #pragma unroll
    for (int mi = 0; mi < 4; mi++) {
        #pragma unroll
        for (int ni = 0; ni < 8; ni++) {
            int row = crow + mi * 16 + g;
            int col = ccol + ni * 8 + tq;
            float2 v0 = make_float2(acc[mi][ni][0], acc[mi][ni][1]);
            float2 v1 = make_float2(acc[mi][ni][2], acc[mi][ni][3]);
            if (bias) {
                float2 bv = *(const float2*)(bias + col);
                v0.x += bv.x; v0.y += bv.y; v1.x += bv.x; v1.y += bv.y;
            }
            if (relu) {
                v0.x = fmaxf(v0.x, 0.f); v0.y = fmaxf(v0.y, 0.f);
                v1.x = fmaxf(v1.x, 0.f); v1.y = fmaxf(v1.y, 0.f);
            }
            *(float2*)&C[(size_t)row * N + col]       = v0;
            *(float2*)&C[(size_t)(row + 8) * N + col] = v1;
        }
    }
}

// ---------------------------------------------------------------------------
// LayerNorm (fp32 out)
// ---------------------------------------------------------------------------
__global__ __launch_bounds__(256) void ln_kernel(
    const float* __restrict__ x, const float* __restrict__ g,
    const float* __restrict__ b, float* __restrict__ out)
{
    int row = blockIdx.x;
    const float* xr = x + (size_t)row * D_;
    float s = 0.f, s2 = 0.f;
    #pragma unroll
    for (int i = threadIdx.x; i < D_; i += 256) {
        float v = xr[i]; s += v; s2 += v * v;
    }
    __shared__ float sh[20];
    #pragma unroll
    for (int o = 16; o > 0; o >>= 1) {
        s  += __shfl_down_sync(0xffffffffu, s,  o);
        s2 += __shfl_down_sync(0xffffffffu, s2, o);
    }
    int warp = threadIdx.x >> 5, lane = threadIdx.x & 31;
    if (lane == 0) { sh[warp] = s; sh[warp + 8] = s2; }
    __syncthreads();
    if (threadIdx.x == 0) {
        float ts = 0.f, ts2 = 0.f;
        #pragma unroll
        for (int w = 0; w < 8; w++) { ts += sh[w]; ts2 += sh[w + 8]; }
        float mean = ts * (1.0f / D_);
        float var  = ts2 * (1.0f / D_) - mean * mean;
        sh[16] = mean;
        sh[17] = rsqrtf(var + 1e-5f);
    }
    __syncthreads();
    float mean = sh[16], inv = sh[17];
    float* orow = out + (size_t)row * D_;
    #pragma unroll
    for (int i = threadIdx.x; i < D_; i += 256)
        orow[i] = (xr[i] - mean) * inv * g[i] + b[i];
}

// ---------------------------------------------------------------------------
// Causal flash attention v2: float4 SMEM reads, chunk-16 deferred rescale.
// fp32 in, fp32 out (identical interface to v1). qkv packed [M, 3072].
// ---------------------------------------------------------------------------
#define QKV_S 3072
__global__ __launch_bounds__(128) void attn_kernel(
    const float* __restrict__ qkv, float* __restrict__ o)
{
    __shared__ float4 Ks[64 * 16];
    __shared__ float4 Vs[64 * 16];
    const int bh = blockIdx.y;
    const int bb = bh >> 4, hh = bh & 15;            // batch, head
    const int i  = blockIdx.x * 128 + threadIdx.x;   // query time index
    const size_t colq = (size_t)hh * DH_;

    float qr[DH_];
    const float* qrow = qkv + (size_t)(i * B_ + bb) * QKV_S + colq;
    #pragma unroll
    for (int d = 0; d < DH_; d++) qr[d] = qrow[d] * SCALE_;

    float m = -INFINITY, l = 0.f;
    float acc[DH_];
    #pragma unroll
    for (int d = 0; d < DH_; d++) acc[d] = 0.f;

    const int jend = blockIdx.x * 128 + 127;
    const int jr = threadIdx.x >> 1;
    const int c0 = (threadIdx.x & 1) * 8;            // float4 units

    for (int j0 = 0; j0 <= jend; j0 += 64) {
        const float* kb = qkv + (size_t)((j0 + jr) * B_ + bb) * QKV_S + colq;
        #pragma unroll
        for (int c = 0; c < 8; c++) {
            Ks[jr * 16 + c0 + c] = ((const float4*)(kb + 1024))[c0 + c];
            Vs[jr * 16 + c0 + c] = ((const float4*)(kb + 2048))[c0 + c];
        }
        __syncthreads();

        #pragma unroll
        for (int cb = 0; cb < 64; cb += 16) {
            float p[16];
            float cmax = -INFINITY;
            #pragma unroll
            for (int jj = 0; jj < 16; jj++) {
                const float4* kr = &Ks[(cb + jj) * 16];
                float s = 0.f;
                #pragma unroll
                for (int d4 = 0; d4 < 16; d4++) {
                    float4 f = kr[d4];
                    s = fmaf(qr[4 * d4 + 0], f.x, s);
                    s = fmaf(qr[4 * d4 + 1], f.y, s);
                    s = fmaf(qr[4 * d4 + 2], f.z, s);
                    s = fmaf(qr[4 * d4 + 3], f.w, s);
                }
                int j = j0 + cb + jj;
                s = (j <= i) ? s : -INFINITY;
                p[jj] = s;
                cmax = fmaxf(cmax, s);
            }
            float mn = fmaxf(m, cmax);               // finite after 1st chunk
            float corr = __expf(m - mn);
            float sump = 0.f;
            #pragma unroll
            for (int jj = 0; jj < 16; jj++) {
                p[jj] = __expf(p[jj] - mn);          // masked -> 0
                sump += p[jj];
            }
            l = l * corr + sump;
            #pragma unroll
            for (int d = 0; d < DH_; d++) acc[d] *= corr;
            #pragma unroll
            for (int jj = 0; jj < 16; jj++) {
                float pj = p[jj];
                const float4* vr = &Vs[(cb + jj) * 16];
                #pragma unroll
                for (int d4 = 0; d4 < 16; d4++) {
                    float4 f = vr[d4];
                    acc[4 * d4 + 0] = fmaf(pj, f.x, acc[4 * d4 + 0]);
                    acc[4 * d4 + 1] = fmaf(pj, f.y, acc[4 * d4 + 1]);
                    acc[4 * d4 + 2] = fmaf(pj, f.z, acc[4 * d4 + 2]);
                    acc[4 * d4 + 3] = fmaf(pj, f.w, acc[4 * d4 + 3]);
                }
            }
            m = mn;
        }
        __syncthreads();
    }

    float invl = 1.0f / l;
    float* ob = o + (size_t)(i * B_ + bb) * (H_ * DH_) + colq;
    #pragma unroll
    for (int d = 0; d < DH_; d++) ob[d] = acc[d] * invl;
}

// ---------------------------------------------------------------------------
// GRU gate: yW/xU packed [M, 3072] (r|z|g per row)
// ---------------------------------------------------------------------------
__global__ __launch_bounds__(256) void gru_kernel(
    const float* __restrict__ x,
    const float* __restrict__ yW, const float* __restrict__ xU,
    const float* __restrict__ bz, float* __restrict__ out)
{
    int idx = blockIdx.x * 256 + threadIdx.x;
    int row = idx >> 10, d = idx & (D_ - 1);
    size_t b = (size_t)row * 3072 + d;
    float r = 1.0f / (1.0f + expf(-(yW[b] + xU[b])));
    float z = 1.0f / (1.0f + expf(-(yW[b + 1024] + xU[b + 1024] + bz[d] - BG_)));
    float h = tanhf(yW[b + 2048] + r * xU[b + 2048]);
    out[idx] = (1.0f - z) * x[idx] + z * h;
}

// ---------------------------------------------------------------------------
static void conv_A(const float* src, __half* ah, size_t n) {
    int n4 = (int)(n >> 2);
    convA_kernel<<<(n4 + 255) / 256, 256>>>(src, ah, n4);
}
static void conv_B(const float* w, __half* bh, int K, int N, size_t outRowOff) {
    dim3 g(N / 32, K / 32), b(32, 8);
    transB_kernel<<<g, b>>>(w, bh + outRowOff * K, K, N);
}

extern "C" void kernel_launch(void* const* d_in, const int* in_sizes, int n_in,
                              void* d_out, int out_size)
{
    const float* x     = (const float*)d_in[0];
    const float* Wq    = (const float*)d_in[1];
    const float* Wk    = (const float*)d_in[2];
    const float* Wv    = (const float*)d_in[3];
    const float* Wo    = (const float*)d_in[4];
    const float* ln1_g = (const float*)d_in[5];
    const float* ln1_b = (const float*)d_in[6];
    const float* W1    = (const float*)d_in[7];
    const float* b1    = (const float*)d_in[8];
    const float* W2    = (const float*)d_in[9];
    const float* b2    = (const float*)d_in[10];
    const float* ln2_g = (const float*)d_in[11];
    const float* ln2_b = (const float*)d_in[12];
    const float* g1W   = (const float*)d_in[13];
    const float* g1U   = (const float*)d_in[14];
    const float* g1bz  = (const float*)d_in[15];
    const float* g2W   = (const float*)d_in[16];
    const float* g2U   = (const float*)d_in[17];
    const float* g2bz  = (const float*)d_in[18];
    float* out = (float*)d_out;

    float* buf = nullptr;
    __half *Ah, *Bh;
    cudaGetSymbolAddress((void**)&buf, g_buf);
    cudaGetSymbolAddress((void**)&Ah, g_Ah);
    cudaGetSymbolAddress((void**)&Bh, g_Bh);

    float* xn    = buf + 0ull  * MD_;
    float* qkv   = buf + 1ull  * MD_;   // [M, 3072]
    float* attnb = buf + 4ull  * MD_;
    float* y     = buf + 5ull  * MD_;
    float* yW    = buf + 6ull  * MD_;   // [M, 3072]
    float* xU    = buf + 9ull  * MD_;   // [M, 3072]
    float* src   = buf + 12ull * MD_;
    float* sn    = buf + 13ull * MD_;
    float* ffo   = buf + 14ull * MD_;
    float* ff1   = buf + 15ull * MD_;   // [M, 4096]

    cudaFuncSetAttribute(mma_gemm, cudaFuncAttributeMaxDynamicSharedMemorySize,
                         GEMM_SMEM);

    const size_t DD = (size_t)D_ * D_;
    const dim3 g3(3072 / BN, M_ / BM);    // (24, 32)
    const dim3 g1k(1024 / BN, M_ / BM);   // (8, 32)
    const dim3 g4k(4096 / BN, M_ / BM);   // (32, 32)

    // --- LN1 + QKV (fused N=3072) ---
    ln_kernel<<<M_, 256>>>(x, ln1_g, ln1_b, xn);
    conv_A(xn, Ah, (size_t)MD_);
    conv_B(Wq, Bh, D_, D_, 0);
    conv_B(Wk, Bh, D_, D_, 1024);
    conv_B(Wv, Bh, D_, D_, 2048);
    mma_gemm<<<g3, 256, GEMM_SMEM>>>(Ah, Bh, qkv, M_, 3072, D_, nullptr, 0);

    // --- attention (v2) ---
    attn_kernel<<<dim3(T_ / 128, B_ * H_), 128>>>(qkv, attnb);

    // --- output projection ---
    conv_A(attnb, Ah, (size_t)MD_);
    conv_B(Wo, Bh, D_, D_, 0);
    mma_gemm<<<g1k, 256, GEMM_SMEM>>>(Ah, Bh, y, M_, 1024, D_, nullptr, 0);

    // --- GRU gate 1 ---
    conv_A(y, Ah, (size_t)MD_);
    for (int i = 0; i < 3; i++) conv_B(g1W + i * DD, Bh, D_, D_, (size_t)i * 1024);
    mma_gemm<<<g3, 256, GEMM_SMEM>>>(Ah, Bh, yW, M_, 3072, D_, nullptr, 0);
    conv_A(x, Ah, (size_t)MD_);
    for (int i = 0; i < 3; i++) conv_B(g1U + i * DD, Bh, D_, D_, (size_t)i * 1024);
    mma_gemm<<<g3, 256, GEMM_SMEM>>>(Ah, Bh, xU, M_, 3072, D_, nullptr, 0);
    gru_kernel<<<MD_ / 256, 256>>>(x, yW, xU, g1bz, src);

    // --- LN2 + FFN ---
    ln_kernel<<<M_, 256>>>(src, ln2_g, ln2_b, sn);
    conv_A(sn, Ah, (size_t)MD_);
    conv_B(W1, Bh, D_, FF_, 0);
    mma_gemm<<<g4k, 256, GEMM_SMEM>>>(Ah, Bh, ff1, M_, 4096, D_, b1, 1);
    conv_A(ff1, Ah, (size_t)M_ * FF_);
    conv_B(W2, Bh, FF_, D_, 0);
    mma_gemm<<<g1k, 256, GEMM_SMEM>>>(Ah, Bh, ffo, M_, 1024, FF_, b2, 0);

    // --- GRU gate 2 ---
    conv_A(ffo, Ah, (size_t)MD_);
    for (int i = 0; i < 3; i++) conv_B(g2W + i * DD, Bh, D_, D_, (size_t)i * 1024);
    mma_gemm<<<g3, 256, GEMM_SMEM>>>(Ah, Bh, yW, M_, 3072, D_, nullptr, 0);
    conv_A(src, Ah, (size_t)MD_);
    for (int i = 0; i < 3; i++) conv_B(g2U + i * DD, Bh, D_, D_, (size_t)i * 1024);
    mma_gemm<<<g3, 256, GEMM_SMEM>>>(Ah, Bh, xU, M_, 3072, D_, nullptr, 0);
    gru_kernel<<<MD_ / 256, 256>>>(src, yW, xU, g2bz, out);
}

// round 16
// speedup vs baseline: 1.1950x; 1.1950x over previous
#include <cuda_runtime.h>
#include <cuda_fp16.h>
#include <math.h>
#include <stdint.h>

// Problem constants
#define T_   1024
#define B_   8
#define D_   1024
#define H_   16
#define DH_  64
#define FF_  4096
#define M_   (T_ * B_)          // 8192
#define MD_  (8388608)          // M_ * D_
#define SCALE_ 0.125f
#define BG_  0.1f

// fp32 scratch (10 * MD): 0-2 qkv, 3-5 yW, 6-8 xU, 9 src
__device__ float g_buf[10ull * 8388608ull];
// fp16 operand scratch (11 * MD):
// 0:xn 1:attn 2:y 3:x 4:sn 5-8:ff1 9:ffo 10:src
__device__ __half g_h[11ull * 8388608ull];
// fp16 weight scratch [N,K]
__device__ __half g_Bh[4194304];

// ---------------------------------------------------------------------------
// PTX helpers
// ---------------------------------------------------------------------------
__device__ __forceinline__ uint32_t smem_u32(const void* p) {
    uint32_t a;
    asm("{ .reg .u64 t; cvta.to.shared.u64 t, %1; cvt.u32.u64 %0, t; }"
        : "=r"(a) : "l"(p));
    return a;
}
__device__ __forceinline__ void cp16(uint32_t s, const void* g) {
    asm volatile("cp.async.cg.shared.global [%0], [%1], 16;" :: "r"(s), "l"(g));
}
__device__ __forceinline__ void cp_commit() {
    asm volatile("cp.async.commit_group;" ::: "memory");
}
__device__ __forceinline__ void cp_wait1() {
    asm volatile("cp.async.wait_group 1;" ::: "memory");
}
__device__ __forceinline__ void ldsm4(uint32_t (&r)[4], uint32_t addr) {
    asm volatile("ldmatrix.sync.aligned.m8n8.x4.shared.b16 {%0,%1,%2,%3}, [%4];"
        : "=r"(r[0]), "=r"(r[1]), "=r"(r[2]), "=r"(r[3]) : "r"(addr));
}
// fp16 MMA, fp32 accumulate
#define MMA(d, a, b) \
    asm volatile("mma.sync.aligned.m16n8k16.row.col.f32.f16.f16.f32 " \
        "{%0,%1,%2,%3}, {%4,%5,%6,%7}, {%8,%9}, {%0,%1,%2,%3};" \
        : "+f"((d)[0]), "+f"((d)[1]), "+f"((d)[2]), "+f"((d)[3]) \
        : "r"((a)[0]), "r"((a)[1]), "r"((a)[2]), "r"((a)[3]), \
          "r"((b)[0]), "r"((b)[1]))

// ---------------------------------------------------------------------------
// fp32 -> fp16 convert (only needed for the raw input x)
// ---------------------------------------------------------------------------
__global__ __launch_bounds__(256) void convA_kernel(
    const float* __restrict__ in, __half* __restrict__ oh, int n4)
{
    int i = blockIdx.x * 256 + threadIdx.x;
    if (i >= n4) return;
    float4 v = ((const float4*)in)[i];
    ((__half2*)oh)[2 * i]     = __floats2half2_rn(v.x, v.y);
    ((__half2*)oh)[2 * i + 1] = __floats2half2_rn(v.z, v.w);
}

// ---------------------------------------------------------------------------
// Weight transpose + fp16 convert: fp32 [K,N] -> fp16 [N,K]
// ---------------------------------------------------------------------------
__global__ __launch_bounds__(256) void transB_kernel(
    const float* __restrict__ in, __half* __restrict__ oh, int Kd, int Nd)
{
    __shared__ float t[32][33];
    int n0 = blockIdx.x * 32, k0 = blockIdx.y * 32;
    int tx = threadIdx.x, ty = threadIdx.y;      // (32, 8)
    #pragma unroll
    for (int j = 0; j < 32; j += 8)
        t[ty + j][tx] = in[(size_t)(k0 + ty + j) * Nd + n0 + tx];
    __syncthreads();
    #pragma unroll
    for (int j = 0; j < 32; j += 8) {
        size_t o = (size_t)(n0 + ty + j) * Kd + k0 + tx;
        oh[o] = __float2half_rn(t[tx][ty + j]);
    }
}

// ---------------------------------------------------------------------------
// fp16 GEMM: C[M,N] = A[M,K] @ B[N,K]^T  (fp32 accumulate)
// CTA 256x128x32, 8 warps (64x64 each), 3-stage cp.async, 1 barrier/K-tile.
// OHALF=0: fp32 output C; OHALF=1: fp16 output Ch (round-identical to
// fp32-store + convA). Fused bias/relu.
// ---------------------------------------------------------------------------
#define BM 256
#define BN 128
#define BK 32
#define STAGES 3
#define AROW 40                                // padded row stride (fp16)
#define A_BYTES (BM * AROW * 2)                // 20480
#define B_BYTES (BN * AROW * 2)                // 10240
#define STG_BYTES (A_BYTES + B_BYTES)          // 30720
#define GEMM_SMEM (STAGES * STG_BYTES)         // 92160

template<int OHALF>
__global__ __launch_bounds__(256) void mma_gemm(
    const __half* __restrict__ Ah, const __half* __restrict__ Bh,
    float* __restrict__ C, __half* __restrict__ Ch,
    int M, int N, int K, const float* __restrict__ bias, int relu)
{
    extern __shared__ char smem[];
    const uint32_t sbase = smem_u32(smem);
    const int tid = threadIdx.x, wid = tid >> 5, lane = tid & 31;
    const int wm = wid & 3, wn = wid >> 2;          // warp tile 64m x 64n
    const size_t arow0 = (size_t)blockIdx.y * BM;
    const size_t brow0 = (size_t)blockIdx.x * BN;
    const __half* gA = Ah + arow0 * K;
    const __half* gB = Bh + brow0 * K;
    const int KT = K / BK;

    auto load_stage = [&](int t) {
        uint32_t sb = sbase + (uint32_t)(t % STAGES) * STG_BYTES;
        size_t ko = (size_t)t * BK;
        #pragma unroll
        for (int j = 0; j < 4; j++) {              // A: 1024 16B-chunks
            int cid = tid + j * 256;
            int row = cid >> 2, c16 = cid & 3;
            cp16(sb + (uint32_t)(row * AROW + c16 * 8) * 2,
                 (const char*)(gA + (size_t)row * K + ko) + c16 * 16);
        }
        #pragma unroll
        for (int j = 0; j < 2; j++) {              // B: 512 chunks
            int cid = tid + j * 256;
            int row = cid >> 2, c16 = cid & 3;
            cp16(sb + A_BYTES + (uint32_t)(row * AROW + c16 * 8) * 2,
                 (const char*)(gB + (size_t)row * K + ko) + c16 * 16);
        }
        cp_commit();
    };

    load_stage(0);
    load_stage(1);

    float acc[4][8][4];
    #pragma unroll
    for (int i = 0; i < 4; i++)
        #pragma unroll
        for (int j = 0; j < 8; j++)
            #pragma unroll
            for (int q = 0; q < 4; q++) acc[i][j][q] = 0.f;

    const int lrowA = lane & 15, lcolA = (lane >> 4) * 8;
    const int lrowB = (lane & 7) + ((lane >> 4) << 3);
    const int lcolB = ((lane >> 3) & 1) * 8;

    for (int t = 0; t < KT; t++) {
        cp_wait1();
        __syncthreads();
        if (t + 2 < KT) load_stage(t + 2);

        uint32_t sb = sbase + (uint32_t)(t % STAGES) * STG_BYTES;
        uint32_t sA = sb, sB = sb + A_BYTES;

        #pragma unroll
        for (int kk = 0; kk < BK; kk += 16) {
            uint32_t aH[4][4], bH[8][2];
            #pragma unroll
            for (int mi = 0; mi < 4; mi++) {
                uint32_t off =
                    (uint32_t)((wm * 64 + mi * 16 + lrowA) * AROW + kk + lcolA) * 2;
                ldsm4(aH[mi], sA + off);
            }
            #pragma unroll
            for (int np = 0; np < 4; np++) {
                uint32_t off =
                    (uint32_t)((wn * 64 + np * 16 + lrowB) * AROW + kk + lcolB) * 2;
                uint32_t r[4];
                ldsm4(r, sB + off);
                bH[2 * np][0] = r[0]; bH[2 * np][1] = r[1];
                bH[2 * np + 1][0] = r[2]; bH[2 * np + 1][1] = r[3];
            }
            #pragma unroll
            for (int mi = 0; mi < 4; mi++)
                #pragma unroll
                for (int ni = 0; ni < 8; ni++)
                    MMA(acc[mi][ni], aH[mi], bH[ni]);
        }
    }

    // epilogue: fused bias/relu; fp32 or fp16 (round-identical) stores
    const int g = lane >> 2, tq = (lane & 3) * 2;
    const int crow = blockIdx.y * BM + wm * 64;
    const int ccol = blockIdx.x * BN + wn * 64;
    #pragma unroll
    for (int mi = 0; mi < 4; mi++) {
        #pragma unroll
        for (int ni = 0; ni < 8; ni++) {
            int row = crow + mi * 16 + g;
            int col = ccol + ni * 8 + tq;
            float2 v0 = make_float2(acc[mi][ni][0], acc[mi][ni][1]);
            float2 v1 = make_float2(acc[mi][ni][2], acc[mi][ni][3]);
            if (bias) {
                float2 bv = *(const float2*)(bias + col);
                v0.x += bv.x; v0.y += bv.y; v1.x += bv.x; v1.y += bv.y;
            }
            if (relu) {
                v0.x = fmaxf(v0.x, 0.f); v0.y = fmaxf(v0.y, 0.f);
                v1.x = fmaxf(v1.x, 0.f); v1.y = fmaxf(v1.y, 0.f);
            }
            if (OHALF == 0) {
                *(float2*)&C[(size_t)row * N + col]       = v0;
                *(float2*)&C[(size_t)(row + 8) * N + col] = v1;
            } else {
                *(__half2*)&Ch[(size_t)row * N + col] =
                    __floats2half2_rn(v0.x, v0.y);
                *(__half2*)&Ch[(size_t)(row + 8) * N + col] =
                    __floats2half2_rn(v1.x, v1.y);
            }
        }
    }
}

// ---------------------------------------------------------------------------
// LayerNorm with fp16 output (round-identical to fp32-out + convA)
// ---------------------------------------------------------------------------
__global__ __launch_bounds__(256) void ln_h_kernel(
    const float* __restrict__ x, const float* __restrict__ g,
    const float* __restrict__ b, __half* __restrict__ oh)
{
    int row = blockIdx.x;
    const float* xr = x + (size_t)row * D_;
    float s = 0.f, s2 = 0.f;
    #pragma unroll
    for (int i = threadIdx.x; i < D_; i += 256) {
        float v = xr[i]; s += v; s2 += v * v;
    }
    __shared__ float sh[20];
    #pragma unroll
    for (int o = 16; o > 0; o >>= 1) {
        s  += __shfl_down_sync(0xffffffffu, s,  o);
        s2 += __shfl_down_sync(0xffffffffu, s2, o);
    }
    int warp = threadIdx.x >> 5, lane = threadIdx.x & 31;
    if (lane == 0) { sh[warp] = s; sh[warp + 8] = s2; }
    __syncthreads();
    if (threadIdx.x == 0) {
        float ts = 0.f, ts2 = 0.f;
        #pragma unroll
        for (int w = 0; w < 8; w++) { ts += sh[w]; ts2 += sh[w + 8]; }
        float mean = ts * (1.0f / D_);
        float var  = ts2 * (1.0f / D_) - mean * mean;
        sh[16] = mean;
        sh[17] = rsqrtf(var + 1e-5f);
    }
    __syncthreads();
    float mean = sh[16], inv = sh[17];
    __half* orow = oh + (size_t)row * D_;
    #pragma unroll
    for (int i = threadIdx.x; i < D_; i += 256)
        orow[i] = __float2half_rn((xr[i] - mean) * inv * g[i] + b[i]);
}

// ---------------------------------------------------------------------------
// Causal flash attention v1 (proven loop body), fp16 output.
// qkv packed [M, 3072] (row = t*B + b).
// ---------------------------------------------------------------------------
#define QKV_S 3072
__global__ __launch_bounds__(128) void attn_kernel(
    const float* __restrict__ qkv, __half* __restrict__ oh)
{
    __shared__ float Ks[64][64];
    __shared__ float Vs[64][64];
    const int bh = blockIdx.y;
    const int bb = bh >> 4, hh = bh & 15;            // batch, head
    const int i  = blockIdx.x * 128 + threadIdx.x;   // query time index
    const size_t colq = (size_t)hh * DH_;

    float qr[DH_];
    #pragma unroll
    for (int d = 0; d < DH_; d++)
        qr[d] = qkv[(size_t)(i * B_ + bb) * QKV_S + colq + d] * SCALE_;

    float m = -INFINITY, l = 0.f;
    float acc[DH_];
    #pragma unroll
    for (int d = 0; d < DH_; d++) acc[d] = 0.f;

    const int jend = blockIdx.x * 128 + 127;
    const int jr = threadIdx.x >> 1;
    const int c0 = (threadIdx.x & 1) * 32;

    for (int j0 = 0; j0 <= jend; j0 += 64) {
        const size_t gro = (size_t)((j0 + jr) * B_ + bb) * QKV_S + colq + c0;
        #pragma unroll
        for (int c = 0; c < 32; c += 4) {
            *(float4*)&Ks[jr][c0 + c] = *(const float4*)&qkv[gro + 1024 + c];
            *(float4*)&Vs[jr][c0 + c] = *(const float4*)&qkv[gro + 2048 + c];
        }
        __syncthreads();
        int jn = i - j0 + 1;
        if (jn > 64) jn = 64;
        for (int jj = 0; jj < jn; jj++) {
            float s = 0.f;
            #pragma unroll
            for (int d = 0; d < DH_; d++) s = fmaf(qr[d], Ks[jj][d], s);
            float mn   = fmaxf(m, s);
            float corr = __expf(m - mn);
            float p    = __expf(s - mn);
            l = l * corr + p;
            #pragma unroll
            for (int d = 0; d < DH_; d++)
                acc[d] = fmaf(acc[d], corr, p * Vs[jj][d]);
            m = mn;
        }
        __syncthreads();
    }
    float invl = 1.0f / l;
    __half* ob = oh + (size_t)(i * B_ + bb) * (H_ * DH_) + colq;
    #pragma unroll
    for (int d = 0; d < DH_; d += 2)
        *(__half2*)&ob[d] = __floats2half2_rn(acc[d] * invl, acc[d + 1] * invl);
}

// ---------------------------------------------------------------------------
// GRU gate: yW/xU packed [M, 3072] (r|z|g). Optional fp16 copy of output.
// ---------------------------------------------------------------------------
__global__ __launch_bounds__(256) void gru_kernel(
    const float* __restrict__ x,
    const float* __restrict__ yW, const float* __restrict__ xU,
    const float* __restrict__ bz, float* __restrict__ out,
    __half* __restrict__ oh)
{
    int idx = blockIdx.x * 256 + threadIdx.x;
    int row = idx >> 10, d = idx & (D_ - 1);
    size_t b = (size_t)row * 3072 + d;
    float r = 1.0f / (1.0f + expf(-(yW[b] + xU[b])));
    float z = 1.0f / (1.0f + expf(-(yW[b + 1024] + xU[b + 1024] + bz[d] - BG_)));
    float h = tanhf(yW[b + 2048] + r * xU[b + 2048]);
    float v = (1.0f - z) * x[idx] + z * h;
    out[idx] = v;
    if (oh) oh[idx] = __float2half_rn(v);
}

// ---------------------------------------------------------------------------
static void conv_B(const float* w, __half* bh, int K, int N, size_t outRowOff) {
    dim3 g(N / 32, K / 32), b(32, 8);
    transB_kernel<<<g, b>>>(w, bh + outRowOff * K, K, N);
}

extern "C" void kernel_launch(void* const* d_in, const int* in_sizes, int n_in,
                              void* d_out, int out_size)
{
    const float* x     = (const float*)d_in[0];
    const float* Wq    = (const float*)d_in[1];
    const float* Wk    = (const float*)d_in[2];
    const float* Wv    = (const float*)d_in[3];
    const float* Wo    = (const float*)d_in[4];
    const float* ln1_g = (const float*)d_in[5];
    const float* ln1_b = (const float*)d_in[6];
    const float* W1    = (const float*)d_in[7];
    const float* b1    = (const float*)d_in[8];
    const float* W2    = (const float*)d_in[9];
    const float* b2    = (const float*)d_in[10];
    const float* ln2_g = (const float*)d_in[11];
    const float* ln2_b = (const float*)d_in[12];
    const float* g1W   = (const float*)d_in[13];
    const float* g1U   = (const float*)d_in[14];
    const float* g1bz  = (const float*)d_in[15];
    const float* g2W   = (const float*)d_in[16];
    const float* g2U   = (const float*)d_in[17];
    const float* g2bz  = (const float*)d_in[18];
    float* out = (float*)d_out;

    float* buf = nullptr;
    __half *hb = nullptr, *Bh = nullptr;
    cudaGetSymbolAddress((void**)&buf, g_buf);
    cudaGetSymbolAddress((void**)&hb, g_h);
    cudaGetSymbolAddress((void**)&Bh, g_Bh);

    float* qkv = buf + 0ull * MD_;      // [M, 3072]
    float* yW  = buf + 3ull * MD_;      // [M, 3072]
    float* xU  = buf + 6ull * MD_;      // [M, 3072]
    float* src = buf + 9ull * MD_;

    __half* xnh  = hb + 0ull  * MD_;
    __half* ath  = hb + 1ull  * MD_;
    __half* yh   = hb + 2ull  * MD_;
    __half* xh   = hb + 3ull  * MD_;
    __half* snh  = hb + 4ull  * MD_;
    __half* f1h  = hb + 5ull  * MD_;    // [M, 4096]
    __half* foh  = hb + 9ull  * MD_;
    __half* srch = hb + 10ull * MD_;

    cudaFuncSetAttribute(mma_gemm<0>, cudaFuncAttributeMaxDynamicSharedMemorySize,
                         GEMM_SMEM);
    cudaFuncSetAttribute(mma_gemm<1>, cudaFuncAttributeMaxDynamicSharedMemorySize,
                         GEMM_SMEM);

    const size_t DD = (size_t)D_ * D_;
    const dim3 g3(3072 / BN, M_ / BM);    // (24, 32)
    const dim3 g1k(1024 / BN, M_ / BM);   // (8, 32)
    const dim3 g4k(4096 / BN, M_ / BM);   // (32, 32)

    // --- LN1 (fp16 out) + QKV (fused N=3072, fp32 out) ---
    ln_h_kernel<<<M_, 256>>>(x, ln1_g, ln1_b, xnh);
    conv_B(Wq, Bh, D_, D_, 0);
    conv_B(Wk, Bh, D_, D_, 1024);
    conv_B(Wv, Bh, D_, D_, 2048);
    mma_gemm<0><<<g3, 256, GEMM_SMEM>>>(xnh, Bh, qkv, nullptr,
                                        M_, 3072, D_, nullptr, 0);

    // --- attention (v1 body, fp16 out) ---
    attn_kernel<<<dim3(T_ / 128, B_ * H_), 128>>>(qkv, ath);

    // --- output projection (fp16 out) ---
    conv_B(Wo, Bh, D_, D_, 0);
    mma_gemm<1><<<g1k, 256, GEMM_SMEM>>>(ath, Bh, nullptr, yh,
                                         M_, 1024, D_, nullptr, 0);

    // --- GRU gate 1 ---
    for (int i = 0; i < 3; i++) conv_B(g1W + i * DD, Bh, D_, D_, (size_t)i * 1024);
    mma_gemm<0><<<g3, 256, GEMM_SMEM>>>(yh, Bh, yW, nullptr,
                                        M_, 3072, D_, nullptr, 0);
    convA_kernel<<<MD_ / 1024, 256>>>(x, xh, MD_ / 4);
    for (int i = 0; i < 3; i++) conv_B(g1U + i * DD, Bh, D_, D_, (size_t)i * 1024);
    mma_gemm<0><<<g3, 256, GEMM_SMEM>>>(xh, Bh, xU, nullptr,
                                        M_, 3072, D_, nullptr, 0);
    gru_kernel<<<MD_ / 256, 256>>>(x, yW, xU, g1bz, src, srch);

    // --- LN2 (fp16 out) + FFN ---
    ln_h_kernel<<<M_, 256>>>(src, ln2_g, ln2_b, snh);
    conv_B(W1, Bh, D_, FF_, 0);
    mma_gemm<1><<<g4k, 256, GEMM_SMEM>>>(snh, Bh, nullptr, f1h,
                                         M_, 4096, D_, b1, 1);
    conv_B(W2, Bh, FF_, D_, 0);
    mma_gemm<1><<<g1k, 256, GEMM_SMEM>>>(f1h, Bh, nullptr, foh,
                                         M_, 1024, FF_, b2, 0);

    // --- GRU gate 2 ---
    for (int i = 0; i < 3; i++) conv_B(g2W + i * DD, Bh, D_, D_, (size_t)i * 1024);
    mma_gemm<0><<<g3, 256, GEMM_SMEM>>>(foh, Bh, yW, nullptr,
                                        M_, 3072, D_, nullptr, 0);
    for (int i = 0; i < 3; i++) conv_B(g2U + i * DD, Bh, D_, D_, (size_t)i * 1024);
    mma_gemm<0><<<g3, 256, GEMM_SMEM>>>(srch, Bh, xU, nullptr,
                                        M_, 3072, D_, nullptr, 0);
    gru_kernel<<<MD_ / 256, 256>>>(src, yW, xU, g2bz, out, nullptr);
}

// round 17
// speedup vs baseline: 1.2237x; 1.0240x over previous
#include <cuda_runtime.h>
#include <cuda_fp16.h>
#include <math.h>
#include <stdint.h>

// Problem constants
#define T_   1024
#define B_   8
#define D_   1024
#define H_   16
#define DH_  64
#define FF_  4096
#define M_   (T_ * B_)          // 8192
#define MD_  (8388608)          // M_ * D_
#define SCALE_ 0.125f
#define BG_  0.1f

// fp32 scratch (10 * MD): 0-2 qkv, 3-5 yW, 6-8 xU, 9 src
__device__ float g_buf[10ull * 8388608ull];
// fp16 operand scratch (11 * MD):
// 0:xn 1:attn 2:y 3:x 4:sn 5-8:ff1 9:ffo 10:src
__device__ __half g_h[11ull * 8388608ull];
// fp16 weight scratch [N,K]
__device__ __half g_Bh[4194304];

// ---------------------------------------------------------------------------
// PTX helpers
// ---------------------------------------------------------------------------
__device__ __forceinline__ uint32_t smem_u32(const void* p) {
    uint32_t a;
    asm("{ .reg .u64 t; cvta.to.shared.u64 t, %1; cvt.u32.u64 %0, t; }"
        : "=r"(a) : "l"(p));
    return a;
}
__device__ __forceinline__ void cp16(uint32_t s, const void* g) {
    asm volatile("cp.async.cg.shared.global [%0], [%1], 16;" :: "r"(s), "l"(g));
}
__device__ __forceinline__ void cp_commit() {
    asm volatile("cp.async.commit_group;" ::: "memory");
}
__device__ __forceinline__ void cp_wait1() {
    asm volatile("cp.async.wait_group 1;" ::: "memory");
}
__device__ __forceinline__ void ldsm4(uint32_t (&r)[4], uint32_t addr) {
    asm volatile("ldmatrix.sync.aligned.m8n8.x4.shared.b16 {%0,%1,%2,%3}, [%4];"
        : "=r"(r[0]), "=r"(r[1]), "=r"(r[2]), "=r"(r[3]) : "r"(addr));
}
// fp16 MMA, fp32 accumulate
#define MMA(d, a, b) \
    asm volatile("mma.sync.aligned.m16n8k16.row.col.f32.f16.f16.f32 " \
        "{%0,%1,%2,%3}, {%4,%5,%6,%7}, {%8,%9}, {%0,%1,%2,%3};" \
        : "+f"((d)[0]), "+f"((d)[1]), "+f"((d)[2]), "+f"((d)[3]) \
        : "r"((a)[0]), "r"((a)[1]), "r"((a)[2]), "r"((a)[3]), \
          "r"((b)[0]), "r"((b)[1]))

// HW tanh (sm_75+), ~2^-11 relative error
__device__ __forceinline__ float tanh_ap(float x) {
    float y;
    asm("tanh.approx.f32 %0, %1;" : "=f"(y) : "f"(x));
    return y;
}
// sigmoid via exact identity sigmoid(u) = 0.5*(1 + tanh(u/2))
__device__ __forceinline__ float sig_ap(float u) {
    return fmaf(tanh_ap(0.5f * u), 0.5f, 0.5f);
}

// ---------------------------------------------------------------------------
// fp32 -> fp16 convert (only needed for the raw input x)
// ---------------------------------------------------------------------------
__global__ __launch_bounds__(256) void convA_kernel(
    const float* __restrict__ in, __half* __restrict__ oh, int n4)
{
    int i = blockIdx.x * 256 + threadIdx.x;
    if (i >= n4) return;
    float4 v = ((const float4*)in)[i];
    ((__half2*)oh)[2 * i]     = __floats2half2_rn(v.x, v.y);
    ((__half2*)oh)[2 * i + 1] = __floats2half2_rn(v.z, v.w);
}

// ---------------------------------------------------------------------------
// Weight transpose + fp16 convert, batched over blockIdx.z (up to 3 weights):
// fp32 [Kd,Nd] -> fp16 [Nd,Kd], output z-slice at oh + z*Nd*Kd.
// ---------------------------------------------------------------------------
__global__ __launch_bounds__(256) void transB3_kernel(
    const float* __restrict__ in0, const float* __restrict__ in1,
    const float* __restrict__ in2, __half* __restrict__ oh, int Kd, int Nd)
{
    __shared__ float t[32][33];
    const float* in = (blockIdx.z == 0) ? in0 : (blockIdx.z == 1) ? in1 : in2;
    __half* oz = oh + (size_t)blockIdx.z * Nd * Kd;
    int n0 = blockIdx.x * 32, k0 = blockIdx.y * 32;
    int tx = threadIdx.x, ty = threadIdx.y;      // (32, 8)
    #pragma unroll
    for (int j = 0; j < 32; j += 8)
        t[ty + j][tx] = in[(size_t)(k0 + ty + j) * Nd + n0 + tx];
    __syncthreads();
    #pragma unroll
    for (int j = 0; j < 32; j += 8) {
        size_t o = (size_t)(n0 + ty + j) * Kd + k0 + tx;
        oz[o] = __float2half_rn(t[tx][ty + j]);
    }
}

// ---------------------------------------------------------------------------
// fp16 GEMM: C[M,N] = A[M,K] @ B[N,K]^T  (fp32 accumulate)
// CTA 256x128x32, 8 warps (64x64 each), 3-stage cp.async, 1 barrier/K-tile.
// OHALF=0: fp32 output C; OHALF=1: fp16 output Ch. Fused bias/relu.
// ---------------------------------------------------------------------------
#define BM 256
#define BN 128
#define BK 32
#define STAGES 3
#define AROW 40                                // padded row stride (fp16)
#define A_BYTES (BM * AROW * 2)                // 20480
#define B_BYTES (BN * AROW * 2)                // 10240
#define STG_BYTES (A_BYTES + B_BYTES)          // 30720
#define GEMM_SMEM (STAGES * STG_BYTES)         // 92160

template<int OHALF>
__global__ __launch_bounds__(256) void mma_gemm(
    const __half* __restrict__ Ah, const __half* __restrict__ Bh,
    float* __restrict__ C, __half* __restrict__ Ch,
    int M, int N, int K, const float* __restrict__ bias, int relu)
{
    extern __shared__ char smem[];
    const uint32_t sbase = smem_u32(smem);
    const int tid = threadIdx.x, wid = tid >> 5, lane = tid & 31;
    const int wm = wid & 3, wn = wid >> 2;          // warp tile 64m x 64n
    const size_t arow0 = (size_t)blockIdx.y * BM;
    const size_t brow0 = (size_t)blockIdx.x * BN;
    const __half* gA = Ah + arow0 * K;
    const __half* gB = Bh + brow0 * K;
    const int KT = K / BK;

    auto load_stage = [&](int t) {
        uint32_t sb = sbase + (uint32_t)(t % STAGES) * STG_BYTES;
        size_t ko = (size_t)t * BK;
        #pragma unroll
        for (int j = 0; j < 4; j++) {              // A: 1024 16B-chunks
            int cid = tid + j * 256;
            int row = cid >> 2, c16 = cid & 3;
            cp16(sb + (uint32_t)(row * AROW + c16 * 8) * 2,
                 (const char*)(gA + (size_t)row * K + ko) + c16 * 16);
        }
        #pragma unroll
        for (int j = 0; j < 2; j++) {              // B: 512 chunks
            int cid = tid + j * 256;
            int row = cid >> 2, c16 = cid & 3;
            cp16(sb + A_BYTES + (uint32_t)(row * AROW + c16 * 8) * 2,
                 (const char*)(gB + (size_t)row * K + ko) + c16 * 16);
        }
        cp_commit();
    };

    load_stage(0);
    load_stage(1);

    float acc[4][8][4];
    #pragma unroll
    for (int i = 0; i < 4; i++)
        #pragma unroll
        for (int j = 0; j < 8; j++)
            #pragma unroll
            for (int q = 0; q < 4; q++) acc[i][j][q] = 0.f;

    const int lrowA = lane & 15, lcolA = (lane >> 4) * 8;
    const int lrowB = (lane & 7) + ((lane >> 4) << 3);
    const int lcolB = ((lane >> 3) & 1) * 8;

    for (int t = 0; t < KT; t++) {
        cp_wait1();
        __syncthreads();
        if (t + 2 < KT) load_stage(t + 2);

        uint32_t sb = sbase + (uint32_t)(t % STAGES) * STG_BYTES;
        uint32_t sA = sb, sB = sb + A_BYTES;

        #pragma unroll
        for (int kk = 0; kk < BK; kk += 16) {
            uint32_t aH[4][4], bH[8][2];
            #pragma unroll
            for (int mi = 0; mi < 4; mi++) {
                uint32_t off =
                    (uint32_t)((wm * 64 + mi * 16 + lrowA) * AROW + kk + lcolA) * 2;
                ldsm4(aH[mi], sA + off);
            }
            #pragma unroll
            for (int np = 0; np < 4; np++) {
                uint32_t off =
                    (uint32_t)((wn * 64 + np * 16 + lrowB) * AROW + kk + lcolB) * 2;
                uint32_t r[4];
                ldsm4(r, sB + off);
                bH[2 * np][0] = r[0]; bH[2 * np][1] = r[1];
                bH[2 * np + 1][0] = r[2]; bH[2 * np + 1][1] = r[3];
            }
            #pragma unroll
            for (int mi = 0; mi < 4; mi++)
                #pragma unroll
                for (int ni = 0; ni < 8; ni++)
                    MMA(acc[mi][ni], aH[mi], bH[ni]);
        }
    }

    // epilogue: fused bias/relu; fp32 or fp16 (round-identical) stores
    const int g = lane >> 2, tq = (lane & 3) * 2;
    const int crow = blockIdx.y * BM + wm * 64;
    const int ccol = blockIdx.x * BN + wn * 64;
    #pragma unroll
    for (int mi = 0; mi < 4; mi++) {
        #pragma unroll
        for (int ni = 0; ni < 8; ni++) {
            int row = crow + mi * 16 + g;
            int col = ccol + ni * 8 + tq;
            float2 v0 = make_float2(acc[mi][ni][0], acc[mi][ni][1]);
            float2 v1 = make_float2(acc[mi][ni][2], acc[mi][ni][3]);
            if (bias) {
                float2 bv = *(const float2*)(bias + col);
                v0.x += bv.x; v0.y += bv.y; v1.x += bv.x; v1.y += bv.y;
            }
            if (relu) {
                v0.x = fmaxf(v0.x, 0.f); v0.y = fmaxf(v0.y, 0.f);
                v1.x = fmaxf(v1.x, 0.f); v1.y = fmaxf(v1.y, 0.f);
            }
            if (OHALF == 0) {
                *(float2*)&C[(size_t)row * N + col]       = v0;
                *(float2*)&C[(size_t)(row + 8) * N + col] = v1;
            } else {
                *(__half2*)&Ch[(size_t)row * N + col] =
                    __floats2half2_rn(v0.x, v0.y);
                *(__half2*)&Ch[(size_t)(row + 8) * N + col] =
                    __floats2half2_rn(v1.x, v1.y);
            }
        }
    }
}

// ---------------------------------------------------------------------------
// LayerNorm with fp16 output
// ---------------------------------------------------------------------------
__global__ __launch_bounds__(256) void ln_h_kernel(
    const float* __restrict__ x, const float* __restrict__ g,
    const float* __restrict__ b, __half* __restrict__ oh)
{
    int row = blockIdx.x;
    const float* xr = x + (size_t)row * D_;
    float s = 0.f, s2 = 0.f;
    #pragma unroll
    for (int i = threadIdx.x; i < D_; i += 256) {
        float v = xr[i]; s += v; s2 += v * v;
    }
    __shared__ float sh[20];
    #pragma unroll
    for (int o = 16; o > 0; o >>= 1) {
        s  += __shfl_down_sync(0xffffffffu, s,  o);
        s2 += __shfl_down_sync(0xffffffffu, s2, o);
    }
    int warp = threadIdx.x >> 5, lane = threadIdx.x & 31;
    if (lane == 0) { sh[warp] = s; sh[warp + 8] = s2; }
    __syncthreads();
    if (threadIdx.x == 0) {
        float ts = 0.f, ts2 = 0.f;
        #pragma unroll
        for (int w = 0; w < 8; w++) { ts += sh[w]; ts2 += sh[w + 8]; }
        float mean = ts * (1.0f / D_);
        float var  = ts2 * (1.0f / D_) - mean * mean;
        sh[16] = mean;
        sh[17] = rsqrtf(var + 1e-5f);
    }
    __syncthreads();
    float mean = sh[16], inv = sh[17];
    __half* orow = oh + (size_t)row * D_;
    #pragma unroll
    for (int i = threadIdx.x; i < D_; i += 256)
        orow[i] = __float2half_rn((xr[i] - mean) * inv * g[i] + b[i]);
}

// ---------------------------------------------------------------------------
// Causal flash attention v1 (proven loop body), fp16 output.
// qkv packed [M, 3072] (row = t*B + b).
// ---------------------------------------------------------------------------
#define QKV_S 3072
__global__ __launch_bounds__(128) void attn_kernel(
    const float* __restrict__ qkv, __half* __restrict__ oh)
{
    __shared__ float Ks[64][64];
    __shared__ float Vs[64][64];
    const int bh = blockIdx.y;
    const int bb = bh >> 4, hh = bh & 15;            // batch, head
    const int i  = blockIdx.x * 128 + threadIdx.x;   // query time index
    const size_t colq = (size_t)hh * DH_;

    float qr[DH_];
    #pragma unroll
    for (int d = 0; d < DH_; d++)
        qr[d] = qkv[(size_t)(i * B_ + bb) * QKV_S + colq + d] * SCALE_;

    float m = -INFINITY, l = 0.f;
    float acc[DH_];
    #pragma unroll
    for (int d = 0; d < DH_; d++) acc[d] = 0.f;

    const int jend = blockIdx.x * 128 + 127;
    const int jr = threadIdx.x >> 1;
    const int c0 = (threadIdx.x & 1) * 32;

    for (int j0 = 0; j0 <= jend; j0 += 64) {
        const size_t gro = (size_t)((j0 + jr) * B_ + bb) * QKV_S + colq + c0;
        #pragma unroll
        for (int c = 0; c < 32; c += 4) {
            *(float4*)&Ks[jr][c0 + c] = *(const float4*)&qkv[gro + 1024 + c];
            *(float4*)&Vs[jr][c0 + c] = *(const float4*)&qkv[gro + 2048 + c];
        }
        __syncthreads();
        int jn = i - j0 + 1;
        if (jn > 64) jn = 64;
        for (int jj = 0; jj < jn; jj++) {
            float s = 0.f;
            #pragma unroll
            for (int d = 0; d < DH_; d++) s = fmaf(qr[d], Ks[jj][d], s);
            float mn   = fmaxf(m, s);
            float corr = __expf(m - mn);
            float p    = __expf(s - mn);
            l = l * corr + p;
            #pragma unroll
            for (int d = 0; d < DH_; d++)
                acc[d] = fmaf(acc[d], corr, p * Vs[jj][d]);
            m = mn;
        }
        __syncthreads();
    }
    float invl = 1.0f / l;
    __half* ob = oh + (size_t)(i * B_ + bb) * (H_ * DH_) + colq;
    #pragma unroll
    for (int d = 0; d < DH_; d += 2)
        *(__half2*)&ob[d] = __floats2half2_rn(acc[d] * invl, acc[d + 1] * invl);
}

// ---------------------------------------------------------------------------
// GRU gate, float4-vectorized, tanh.approx activations.
// yW/xU packed [M, 3072] (r|z|g). Optional fp16 copy of output.
// ---------------------------------------------------------------------------
__global__ __launch_bounds__(256) void gru_kernel(
    const float* __restrict__ x,
    const float* __restrict__ yW, const float* __restrict__ xU,
    const float* __restrict__ bz, float* __restrict__ out,
    __half* __restrict__ oh)
{
    int i4 = blockIdx.x * 256 + threadIdx.x;     // float4 index, MD_/4 total
    int row = i4 >> 8;                            // 256 float4 per 1024-col row
    int d4  = i4 & 255;
    size_t b4 = (size_t)row * 768 + d4;           // 3072 floats = 768 float4

    float4 ywr = ((const float4*)yW)[b4];
    float4 xur = ((const float4*)xU)[b4];
    float4 ywz = ((const float4*)yW)[b4 + 256];
    float4 xuz = ((const float4*)xU)[b4 + 256];
    float4 ywh = ((const float4*)yW)[b4 + 512];
    float4 xuh = ((const float4*)xU)[b4 + 512];
    float4 xv  = ((const float4*)x)[i4];
    float4 bzv = ((const float4*)bz)[d4];

    float r0 = sig_ap(ywr.x + xur.x), r1 = sig_ap(ywr.y + xur.y);
    float r2 = sig_ap(ywr.z + xur.z), r3 = sig_ap(ywr.w + xur.w);
    float z0 = sig_ap(ywz.x + xuz.x + bzv.x - BG_);
    float z1 = sig_ap(ywz.y + xuz.y + bzv.y - BG_);
    float z2 = sig_ap(ywz.z + xuz.z + bzv.z - BG_);
    float z3 = sig_ap(ywz.w + xuz.w + bzv.w - BG_);
    float h0 = tanh_ap(fmaf(r0, xuh.x, ywh.x));
    float h1 = tanh_ap(fmaf(r1, xuh.y, ywh.y));
    float h2 = tanh_ap(fmaf(r2, xuh.z, ywh.z));
    float h3 = tanh_ap(fmaf(r3, xuh.w, ywh.w));

    float4 o;
    o.x = fmaf(z0, h0 - xv.x, xv.x);
    o.y = fmaf(z1, h1 - xv.y, xv.y);
    o.z = fmaf(z2, h2 - xv.z, xv.z);
    o.w = fmaf(z3, h3 - xv.w, xv.w);
    ((float4*)out)[i4] = o;
    if (oh) {
        __half2 p0 = __floats2half2_rn(o.x, o.y);
        __half2 p1 = __floats2half2_rn(o.z, o.w);
        uint2 pk;
        pk.x = *(uint32_t*)&p0;
        pk.y = *(uint32_t*)&p1;
        *(uint2*)&oh[(size_t)i4 * 4] = pk;
    }
}

// ---------------------------------------------------------------------------
static void conv_B3(const float* w0, const float* w1, const float* w2,
                    __half* bh, int K, int N, int nz) {
    dim3 g(N / 32, K / 32, nz), b(32, 8);
    transB3_kernel<<<g, b>>>(w0, w1, w2, bh, K, N);
}

extern "C" void kernel_launch(void* const* d_in, const int* in_sizes, int n_in,
                              void* d_out, int out_size)
{
    const float* x     = (const float*)d_in[0];
    const float* Wq    = (const float*)d_in[1];
    const float* Wk    = (const float*)d_in[2];
    const float* Wv    = (const float*)d_in[3];
    const float* Wo    = (const float*)d_in[4];
    const float* ln1_g = (const float*)d_in[5];
    const float* ln1_b = (const float*)d_in[6];
    const float* W1    = (const float*)d_in[7];
    const float* b1    = (const float*)d_in[8];
    const float* W2    = (const float*)d_in[9];
    const float* b2    = (const float*)d_in[10];
    const float* ln2_g = (const float*)d_in[11];
    const float* ln2_b = (const float*)d_in[12];
    const float* g1W   = (const float*)d_in[13];
    const float* g1U   = (const float*)d_in[14];
    const float* g1bz  = (const float*)d_in[15];
    const float* g2W   = (const float*)d_in[16];
    const float* g2U   = (const float*)d_in[17];
    const float* g2bz  = (const float*)d_in[18];
    float* out = (float*)d_out;

    float* buf = nullptr;
    __half *hb = nullptr, *Bh = nullptr;
    cudaGetSymbolAddress((void**)&buf, g_buf);
    cudaGetSymbolAddress((void**)&hb, g_h);
    cudaGetSymbolAddress((void**)&Bh, g_Bh);

    float* qkv = buf + 0ull * MD_;      // [M, 3072]
    float* yW  = buf + 3ull * MD_;      // [M, 3072]
    float* xU  = buf + 6ull * MD_;      // [M, 3072]
    float* src = buf + 9ull * MD_;

    __half* xnh  = hb + 0ull  * MD_;
    __half* ath  = hb + 1ull  * MD_;
    __half* yh   = hb + 2ull  * MD_;
    __half* xh   = hb + 3ull  * MD_;
    __half* snh  = hb + 4ull  * MD_;
    __half* f1h  = hb + 5ull  * MD_;    // [M, 4096]
    __half* foh  = hb + 9ull  * MD_;
    __half* srch = hb + 10ull * MD_;

    cudaFuncSetAttribute(mma_gemm<0>, cudaFuncAttributeMaxDynamicSharedMemorySize,
                         GEMM_SMEM);
    cudaFuncSetAttribute(mma_gemm<1>, cudaFuncAttributeMaxDynamicSharedMemorySize,
                         GEMM_SMEM);

    const size_t DD = (size_t)D_ * D_;
    const dim3 g3(3072 / BN, M_ / BM);    // (24, 32)
    const dim3 g1k(1024 / BN, M_ / BM);   // (8, 32)
    const dim3 g4k(4096 / BN, M_ / BM);   // (32, 32)

    // --- LN1 (fp16 out) + QKV (fused N=3072, fp32 out) ---
    ln_h_kernel<<<M_, 256>>>(x, ln1_g, ln1_b, xnh);
    conv_B3(Wq, Wk, Wv, Bh, D_, D_, 3);
    mma_gemm<0><<<g3, 256, GEMM_SMEM>>>(xnh, Bh, qkv, nullptr,
                                        M_, 3072, D_, nullptr, 0);

    // --- attention (v1 body, fp16 out) ---
    attn_kernel<<<dim3(T_ / 128, B_ * H_), 128>>>(qkv, ath);

    // --- output projection (fp16 out) ---
    conv_B3(Wo, Wo, Wo, Bh, D_, D_, 1);
    mma_gemm<1><<<g1k, 256, GEMM_SMEM>>>(ath, Bh, nullptr, yh,
                                         M_, 1024, D_, nullptr, 0);

    // --- GRU gate 1 ---
    conv_B3(g1W, g1W + DD, g1W + 2 * DD, Bh, D_, D_, 3);
    mma_gemm<0><<<g3, 256, GEMM_SMEM>>>(yh, Bh, yW, nullptr,
                                        M_, 3072, D_, nullptr, 0);
    convA_kernel<<<MD_ / 1024, 256>>>(x, xh, MD_ / 4);
    conv_B3(g1U, g1U + DD, g1U + 2 * DD, Bh, D_, D_, 3);
    mma_gemm<0><<<g3, 256, GEMM_SMEM>>>(xh, Bh, xU, nullptr,
                                        M_, 3072, D_, nullptr, 0);
    gru_kernel<<<MD_ / 1024, 256>>>(x, yW, xU, g1bz, src, srch);

    // --- LN2 (fp16 out) + FFN ---
    ln_h_kernel<<<M_, 256>>>(src, ln2_g, ln2_b, snh);
    conv_B3(W1, W1, W1, Bh, D_, FF_, 1);
    mma_gemm<1><<<g4k, 256, GEMM_SMEM>>>(snh, Bh, nullptr, f1h,
                                         M_, 4096, D_, b1, 1);
    conv_B3(W2, W2, W2, Bh, FF_, D_, 1);
    mma_gemm<1><<<g1k, 256, GEMM_SMEM>>>(f1h, Bh, nullptr, foh,
                                         M_, 1024, FF_, b2, 0);

    // --- GRU gate 2 ---
    conv_B3(g2W, g2W + DD, g2W + 2 * DD, Bh, D_, D_, 3);
    mma_gemm<0><<<g3, 256, GEMM_SMEM>>>(foh, Bh, yW, nullptr,
                                        M_, 3072, D_, nullptr, 0);
    conv_B3(g2U, g2U + DD, g2U + 2 * DD, Bh, D_, D_, 3);
    mma_gemm<0><<<g3, 256, GEMM_SMEM>>>(srch, Bh, xU, nullptr,
                                        M_, 3072, D_, nullptr, 0);
    gru_kernel<<<MD_ / 1024, 256>>>(src, yW, xU, g2bz, out, nullptr);
}